// round 15
// baseline (speedup 1.0000x reference)
#include <cuda_runtime.h>
#include <math.h>

// ---------------------------------------------------------------------------
// ImageSectionRNNCell — B=64, image 512x512x3, grid 16x16, U=256
// out layout: h_new[64*256] | c_new[64*256] | next_section[64*3]
//
// ONE persistent kernel, 128 blocks x 256 threads (single wave, co-resident),
// R12's proven split-K tiles between lightweight grid barriers:
//  S0: blocks 0-63 front (interp+conv -> g_xs, bias-init g_y/g_ns)
//      blocks 64-127 LSTM recurrent partials h0@lstm_rk -> g_zp[8..11]
//  S1: dense partials xs@dw -> g_y (atomicAdd, bias-pre-init), 128 blocks
//  S2: LSTM input partials relu(g_y)@lstm_k -> g_zp[0..7], 128 blocks (k=32)
//  S3: gates: sum 12 slices + lb -> out h/c, blocks 0-63
//  S4: nsc1 partials h@w1 -> g_ns (atomicAdd), 128 blocks
//  S5: nsc2 -> out section, blocks 0-63
// Barriers: per-stage arrive counter + monotonic generation word.
// ---------------------------------------------------------------------------

#define B 64
#define U 256
#define IMGH 512
#define IMGW 512
#define NB 128

__device__ float g_xs[B * 432];         // conv2 output (dense input)
__device__ float g_y [B * U];           // dense pre-act accum (bias-init S0)
__device__ float g_zp[12][B][4 * U];    // LSTM partials, unit-major [b][u*4+g]
__device__ float g_ns[B * U];           // nsc1 pre-act accum (bias-init S0)

__device__ unsigned g_arrive[8][32];    // per-barrier arrive counter (128B rows)
__device__ unsigned g_gen[8][32];       // per-barrier generation (monotonic)

__device__ __forceinline__ float sigmoidf_(float x) {
    return 1.0f / (1.0f + __expf(-x));
}

// ---- grid barrier: 128 blocks, generation-based, self-resetting ----------
__device__ __forceinline__ void gridbar(int s) {
    __syncthreads();
    if (threadIdx.x == 0) {
        __threadfence();                                   // release
        const unsigned gen0 = *(volatile unsigned*)&g_gen[s][0];
        const unsigned old  = atomicAdd(&g_arrive[s][0], 1u);
        if (old == NB - 1) {
            g_arrive[s][0] = 0;                            // reset for replay
            __threadfence();
            atomicAdd(&g_gen[s][0], 1u);
        } else {
            while (*(volatile unsigned*)&g_gen[s][0] == gen0) __nanosleep(64);
        }
        __threadfence();                                   // acquire
    }
    __syncthreads();
}

// ---- LSTM partial tile: KD-deep k, 64 z-cols (ct), -> g_zp[slice] ---------
template <int KD, bool RELU, bool LDCG>
__device__ __forceinline__ void lstm_tile(float* smem,
                                          const float* __restrict__ actbase,
                                          const float* __restrict__ wbase,
                                          int slice, int ct, int t)
{
    constexpr int AP = KD + 4;
    float (*act)[AP] = (float(*)[AP])smem;              // 64 x AP
    float (*wt)[68]  = (float(*)[68])(smem + 64 * AP);  // KD x 68
    constexpr int NV = KD / 4;

    for (int i = t; i < 64 * NV; i += 256) {
        const int row = i / NV;
        const int c4  = i - row * NV;
        float4 v = LDCG ? __ldcg((const float4*)(actbase + row * U + c4 * 4))
                        : *(const float4*)(actbase + row * U + c4 * 4);
        if (RELU) {
            v.x = fmaxf(v.x, 0.f); v.y = fmaxf(v.y, 0.f);
            v.z = fmaxf(v.z, 0.f); v.w = fmaxf(v.w, 0.f);
        }
        *(float4*)&act[row][c4 * 4] = v;
    }
    for (int i = t; i < KD * 16; i += 256) {
        const int row = i >> 4;
        const int c4  = i & 15;
        const float4 w = *(const float4*)(wbase + (size_t)row * 1024 + ct * 64 + c4 * 4);
        *(float4*)&wt[row][c4 * 4] = w;
    }
    __syncthreads();

    const int c4 = t & 15;       // col group: 4 cols ct*64 + c4*4 ..
    const int bq = t >> 4;       // batches bq, bq+16, bq+32, bq+48
    float s0x = 0.f, s0y = 0.f, s0z = 0.f, s0w = 0.f;
    float s1x = 0.f, s1y = 0.f, s1z = 0.f, s1w = 0.f;
    float s2x = 0.f, s2y = 0.f, s2z = 0.f, s2w = 0.f;
    float s3x = 0.f, s3y = 0.f, s3z = 0.f, s3w = 0.f;

    #pragma unroll 4
    for (int kk = 0; kk < KD; kk++) {
        const float4 w = *(const float4*)&wt[kk][c4 * 4];
        const float a0 = act[bq     ][kk];
        const float a1 = act[bq + 16][kk];
        const float a2 = act[bq + 32][kk];
        const float a3 = act[bq + 48][kk];
        s0x += a0 * w.x; s0y += a0 * w.y; s0z += a0 * w.z; s0w += a0 * w.w;
        s1x += a1 * w.x; s1y += a1 * w.y; s1z += a1 * w.z; s1w += a1 * w.w;
        s2x += a2 * w.x; s2y += a2 * w.y; s2z += a2 * w.z; s2w += a2 * w.w;
        s3x += a3 * w.x; s3y += a3 * w.y; s3z += a3 * w.z; s3w += a3 * w.w;
    }

    // unit-major scatter: global col = ct*64 + c4*4 + q
    const int gg = ct >> 2;              // gate 0..3
    const int u0 = (ct & 3) * 64 + c4 * 4;
    {
        float* d = &g_zp[slice][bq][u0 * 4 + gg];
        d[0] = s0x; d[4] = s0y; d[8] = s0z; d[12] = s0w;
    }
    {
        float* d = &g_zp[slice][bq + 16][u0 * 4 + gg];
        d[0] = s1x; d[4] = s1y; d[8] = s1z; d[12] = s1w;
    }
    {
        float* d = &g_zp[slice][bq + 32][u0 * 4 + gg];
        d[0] = s2x; d[4] = s2y; d[8] = s2z; d[12] = s2w;
    }
    {
        float* d = &g_zp[slice][bq + 48][u0 * 4 + gg];
        d[0] = s3x; d[4] = s3y; d[8] = s3z; d[12] = s3w;
    }
}

// ===========================================================================
__global__ __launch_bounds__(256, 1)
void fused_cell(const float* __restrict__ image,
                const float* __restrict__ section,
                const float* __restrict__ c1k, const float* __restrict__ c1b,
                const float* __restrict__ c2k, const float* __restrict__ c2b,
                const float* __restrict__ dw,  const float* __restrict__ db,
                const float* __restrict__ h0,  const float* __restrict__ c0in,
                const float* __restrict__ lk,  const float* __restrict__ lrk,
                const float* __restrict__ lb,
                const float* __restrict__ w1,  const float* __restrict__ b1,
                const float* __restrict__ w2,  const float* __restrict__ b2v,
                float* __restrict__ out)
{
    __shared__ __align__(16) float smem[64 * 68 * 2];   // 34816 B union
    const int bid = blockIdx.x;
    const int t   = threadIdx.x;

    // =======================================================================
    // S0: front (blocks 0-63) || LSTM recurrent partials (blocks 64-127)
    // =======================================================================
    if (bid >= B) {
        const int b2 = bid - B;           // 0..63
        const int ct = b2 & 15;
        const int ks = b2 >> 4;           // 0..3
        lstm_tile<64, false, false>(smem, h0 + ks * 64,
                                    lrk + (size_t)ks * 64 * 1024,
                                    8 + ks, ct, t);
    } else {
        const int b = bid;
        float* sec = smem;                // 768 floats
        float* c1o = smem + 768;          // 588 floats

        g_y [b * U + t] = db[t];
        g_ns[b * U + t] = b1[t];

        {
            const float s0 = section[b * 3 + 0];
            const float s1 = section[b * 3 + 1];
            const float ee = section[b * 3 + 2];
            const int i = t >> 4;
            const int j = t & 15;
            const float p0 = s0 + (float)i * (1.0f / 15.0f) * ee;
            const float p1 = s1 + (float)j * (1.0f / 15.0f) * ee;
            float fy = fminf(fmaxf(p0 * (float)(IMGH - 1), 0.0f), (float)(IMGH - 1));
            float fx = fminf(fmaxf(p1 * (float)(IMGW - 1), 0.0f), (float)(IMGW - 1));
            int y0 = (int)floorf(fy);
            int x0 = (int)floorf(fx);
            int y1 = min(y0 + 1, IMGH - 1);
            int x1 = min(x0 + 1, IMGW - 1);
            float wy = fy - (float)y0;
            float wx = fx - (float)x0;
            const float* img = image + (size_t)b * IMGH * IMGW * 3;
            const float* p00 = img + ((size_t)y0 * IMGW + x0) * 3;
            const float* p01 = img + ((size_t)y0 * IMGW + x1) * 3;
            const float* p10 = img + ((size_t)y1 * IMGW + x0) * 3;
            const float* p11 = img + ((size_t)y1 * IMGW + x1) * 3;
            #pragma unroll
            for (int c = 0; c < 3; c++) {
                float top = p00[c] * (1.0f - wx) + p01[c] * wx;
                float bot = p10[c] * (1.0f - wx) + p11[c] * wx;
                sec[(i * 16 + j) * 3 + c] = top * (1.0f - wy) + bot * wy;
            }
        }
        __syncthreads();

        if (t < 196) {
            const int oh = t / 14;
            const int ow = t - oh * 14;
            float a0 = c1b[0], a1 = c1b[1], a2 = c1b[2];
            #pragma unroll
            for (int kh = 0; kh < 3; kh++)
                #pragma unroll
                for (int kw = 0; kw < 3; kw++) {
                    const float* s = &sec[((oh + kh) * 16 + (ow + kw)) * 3];
                    const float* w = &c1k[(kh * 3 + kw) * 9];
                    #pragma unroll
                    for (int ic = 0; ic < 3; ic++) {
                        const float sv = s[ic];
                        a0 += sv * w[ic * 3 + 0];
                        a1 += sv * w[ic * 3 + 1];
                        a2 += sv * w[ic * 3 + 2];
                    }
                }
            c1o[t * 3 + 0] = fmaxf(a0, 0.0f);
            c1o[t * 3 + 1] = fmaxf(a1, 0.0f);
            c1o[t * 3 + 2] = fmaxf(a2, 0.0f);
        }
        __syncthreads();

        if (t < 144) {
            const int oh = t / 12;
            const int ow = t - oh * 12;
            float a0 = c2b[0], a1 = c2b[1], a2 = c2b[2];
            #pragma unroll
            for (int kh = 0; kh < 3; kh++)
                #pragma unroll
                for (int kw = 0; kw < 3; kw++) {
                    const float* s = &c1o[((oh + kh) * 14 + (ow + kw)) * 3];
                    const float* w = &c2k[(kh * 3 + kw) * 9];
                    #pragma unroll
                    for (int ic = 0; ic < 3; ic++) {
                        const float sv = s[ic];
                        a0 += sv * w[ic * 3 + 0];
                        a1 += sv * w[ic * 3 + 1];
                        a2 += sv * w[ic * 3 + 2];
                    }
                }
            float* dst = g_xs + b * 432 + t * 3;
            dst[0] = fmaxf(a0, 0.0f);
            dst[1] = fmaxf(a1, 0.0f);
            dst[2] = fmaxf(a2, 0.0f);
        }
    }
    gridbar(0);

    // =======================================================================
    // S1: dense partials. 128 blocks = 32 ut (8 units) x 4 kt (108 k).
    // =======================================================================
    {
        float (*axs)[112] = (float(*)[112])smem;               // 64 x 112
        float (*wts)[12]  = (float(*)[12])(smem + 64 * 112);   // 108 x 12
        const int ut = bid & 31;
        const int kt = bid >> 5;
        const int k0 = kt * 108;

        for (int i = t; i < 64 * 27; i += 256) {
            const int row = i / 27;
            const int c4  = i - row * 27;
            const float4 v = __ldcg((const float4*)(g_xs + row * 432 + k0 + c4 * 4));
            *(float4*)&axs[row][c4 * 4] = v;
        }
        if (t < 216) {
            const int row = t >> 1;
            const int h   = t & 1;
            const float4 w = *(const float4*)(dw + (size_t)(k0 + row) * U + ut * 8 + h * 4);
            *(float4*)&wts[row][h * 4] = w;
        }
        __syncthreads();

        const int u2 = t & 3;
        const int bp = t >> 2;
        float a0 = 0.f, a1 = 0.f, a2 = 0.f, a3 = 0.f;
        #pragma unroll 2
        for (int k = 0; k < 108; k += 2) {
            const float x0 = axs[bp][k];
            const float x1 = axs[bp][k + 1];
            const float2 w0 = *(const float2*)&wts[k][u2 * 2];
            const float2 w1 = *(const float2*)&wts[k + 1][u2 * 2];
            a0 += x0 * w0.x; a1 += x0 * w0.y;
            a2 += x1 * w1.x; a3 += x1 * w1.y;
        }
        const int u = ut * 8 + u2 * 2;
        atomicAdd(&g_y[bp * U + u],     a0 + a2);
        atomicAdd(&g_y[bp * U + u + 1], a1 + a3);
    }
    gridbar(1);

    // =======================================================================
    // S2: LSTM input partials. 128 blocks = 16 ct x 8 kt (32-deep k).
    // acts = relu(g_y), weights = lstm_k -> g_zp[0..7]
    // =======================================================================
    {
        const int ct = bid & 15;
        const int kt = bid >> 4;          // 0..7
        lstm_tile<32, true, true>(smem, g_y + kt * 32,
                                  lk + (size_t)kt * 32 * 1024, kt, ct, t);
    }
    gridbar(2);

    // =======================================================================
    // S3: gates. Blocks 0-63: b = bid, u = t. Sum 12 slices + bias, nonlin.
    // =======================================================================
    if (bid < B) {
        const int b = bid;
        const int u = t;
        float zi = 0.f, zf = 0.f, zg = 0.f, zo = 0.f;
        #pragma unroll
        for (int s = 0; s < 12; s++) {
            const float4 z = __ldcg((const float4*)&g_zp[s][b][u * 4]);
            zi += z.x; zf += z.y; zg += z.z; zo += z.w;
        }
        zi += lb[u];
        zf += lb[U + u];
        zg += lb[2 * U + u];
        zo += lb[3 * U + u];

        const float cprev = c0in[b * U + u];
        const float cn = sigmoidf_(zf) * cprev + sigmoidf_(zi) * tanhf(zg);
        const float hn = sigmoidf_(zo) * tanhf(cn);
        out[b * U + u]         = hn;
        out[B * U + b * U + u] = cn;
    }
    gridbar(3);

    // =======================================================================
    // S4: nsc1 partials. 128 blocks = 32 ut (8 units) x 4 kt (64 k).
    // =======================================================================
    {
        float (*axs)[68] = (float(*)[68])smem;               // 64 x 68
        float (*wts)[12] = (float(*)[12])(smem + 64 * 68);   // 64 x 12
        const int ut = bid & 31;
        const int kt = bid >> 5;
        const int k0 = kt * 64;

        for (int i = t; i < 64 * 16; i += 256) {
            const int row = i >> 4;
            const int c4  = i & 15;
            const float4 v = __ldcg((const float4*)(out + row * U + k0 + c4 * 4));
            *(float4*)&axs[row][c4 * 4] = v;
        }
        if (t < 128) {
            const int row = t >> 1;
            const int h   = t & 1;
            const float4 w = *(const float4*)(w1 + (size_t)(k0 + row) * U + ut * 8 + h * 4);
            *(float4*)&wts[row][h * 4] = w;
        }
        __syncthreads();

        const int u2 = t & 3;
        const int bp = t >> 2;
        float a0 = 0.f, a1 = 0.f, a2 = 0.f, a3 = 0.f;
        #pragma unroll 4
        for (int k = 0; k < 64; k += 2) {
            const float x0 = axs[bp][k];
            const float x1 = axs[bp][k + 1];
            const float2 w0 = *(const float2*)&wts[k][u2 * 2];
            const float2 w1v = *(const float2*)&wts[k + 1][u2 * 2];
            a0 += x0 * w0.x;  a1 += x0 * w0.y;
            a2 += x1 * w1v.x; a3 += x1 * w1v.y;
        }
        const int u = ut * 8 + u2 * 2;
        atomicAdd(&g_ns[bp * U + u],     a0 + a2);
        atomicAdd(&g_ns[bp * U + u + 1], a1 + a3);
    }
    gridbar(4);

    // =======================================================================
    // S5: nsc2. Blocks 0-63, warps 0-2: next_section.
    // =======================================================================
    if (bid < B && t < 96) {
        const int b = bid;
        const int g = t >> 5;
        const int l = t & 31;
        float s = 0.0f;
        #pragma unroll
        for (int i = 0; i < 8; i++) {
            const int k = l + i * 32;
            s += fmaxf(__ldcg(&g_ns[b * U + k]), 0.0f) * w2[k * 3 + g];
        }
        #pragma unroll
        for (int o = 16; o > 0; o >>= 1)
            s += __shfl_down_sync(0xffffffffu, s, o);
        if (l == 0)
            out[2 * B * U + b * 3 + g] = sigmoidf_(s + b2v[g]);
    }
}

// ===========================================================================
extern "C" void kernel_launch(void* const* d_in, const int* in_sizes, int n_in,
                              void* d_out, int out_size)
{
    const float* image   = (const float*)d_in[0];
    const float* section = (const float*)d_in[1];
    const float* h0      = (const float*)d_in[2];
    const float* c0      = (const float*)d_in[3];
    const float* conv1_k = (const float*)d_in[4];
    const float* conv1_b = (const float*)d_in[5];
    const float* conv2_k = (const float*)d_in[6];
    const float* conv2_b = (const float*)d_in[7];
    const float* dense_w = (const float*)d_in[8];
    const float* dense_b = (const float*)d_in[9];
    const float* lstm_k  = (const float*)d_in[10];
    const float* lstm_rk = (const float*)d_in[11];
    const float* lstm_b  = (const float*)d_in[12];
    const float* nsc_w1  = (const float*)d_in[13];
    const float* nsc_b1  = (const float*)d_in[14];
    const float* nsc_w2  = (const float*)d_in[15];
    const float* nsc_b2  = (const float*)d_in[16];
    float* out = (float*)d_out;

    fused_cell<<<NB, 256>>>(image, section,
                            conv1_k, conv1_b, conv2_k, conv2_b,
                            dense_w, dense_b,
                            h0, c0, lstm_k, lstm_rk, lstm_b,
                            nsc_w1, nsc_b1, nsc_w2, nsc_b2,
                            out);
}

// round 17
// speedup vs baseline: 1.9106x; 1.9106x over previous
#include <cuda_runtime.h>
#include <math.h>

// ---------------------------------------------------------------------------
// ImageSectionRNNCell — B=64, image 512x512x3, grid 16x16, U=256
// out layout: h_new[64*256] | c_new[64*256] | next_section[64*3]
//
// 4 launches (R12 tiles; tail stages merged per-batch, no cross-block sync):
//  K1 (64x256):  front (interp+conv1+conv2 -> g_xs) + bias-init g_y
//  K2 (128x256): dense partial xs@dw -> g_y (atomicAdd, bias-pre-init)
//  K3 (128x256): LSTM partial (16 col-tile x 8 k-tile) -> g_zp (unit-major)
//  K4 (64x512):  per-batch tail: gates -> out h/c; nsc1 GEMV; nsc2 -> section
// ---------------------------------------------------------------------------

#define B 64
#define U 256
#define IMGH 512
#define IMGW 512

__device__ float g_xs[B * 432];        // conv2 output (dense input)
__device__ float g_y [B * U];          // dense pre-act accumulator (bias-init)
__device__ float g_zp[8][B][4 * U];    // LSTM partials, unit-major [b][u*4+g]

__device__ __forceinline__ float sigmoidf_(float x) {
    return 1.0f / (1.0f + __expf(-x));
}

// ===========================================================================
// K1: bias-init g_y + interpolate + conv1 + conv2 -> g_xs
// ===========================================================================
__global__ __launch_bounds__(256, 4)
void k1_front(const float* __restrict__ image,
              const float* __restrict__ section,
              const float* __restrict__ c1k, const float* __restrict__ c1b,
              const float* __restrict__ c2k, const float* __restrict__ c2b,
              const float* __restrict__ db)
{
    const int b = blockIdx.x;
    const int t = threadIdx.x;

    g_y[b * U + t] = db[t];

    __shared__ float sec[16 * 16 * 3];
    __shared__ float c1o[14 * 14 * 3];

    {
        const float s0 = section[b * 3 + 0];
        const float s1 = section[b * 3 + 1];
        const float ee = section[b * 3 + 2];
        const int i = t >> 4;
        const int j = t & 15;
        const float p0 = s0 + (float)i * (1.0f / 15.0f) * ee;
        const float p1 = s1 + (float)j * (1.0f / 15.0f) * ee;
        float fy = fminf(fmaxf(p0 * (float)(IMGH - 1), 0.0f), (float)(IMGH - 1));
        float fx = fminf(fmaxf(p1 * (float)(IMGW - 1), 0.0f), (float)(IMGW - 1));
        int y0 = (int)floorf(fy);
        int x0 = (int)floorf(fx);
        int y1 = min(y0 + 1, IMGH - 1);
        int x1 = min(x0 + 1, IMGW - 1);
        float wy = fy - (float)y0;
        float wx = fx - (float)x0;
        const float* img = image + (size_t)b * IMGH * IMGW * 3;
        const float* p00 = img + ((size_t)y0 * IMGW + x0) * 3;
        const float* p01 = img + ((size_t)y0 * IMGW + x1) * 3;
        const float* p10 = img + ((size_t)y1 * IMGW + x0) * 3;
        const float* p11 = img + ((size_t)y1 * IMGW + x1) * 3;
        #pragma unroll
        for (int c = 0; c < 3; c++) {
            float top = p00[c] * (1.0f - wx) + p01[c] * wx;
            float bot = p10[c] * (1.0f - wx) + p11[c] * wx;
            sec[(i * 16 + j) * 3 + c] = top * (1.0f - wy) + bot * wy;
        }
    }
    __syncthreads();

    if (t < 196) {
        const int oh = t / 14;
        const int ow = t - oh * 14;
        float a0 = c1b[0], a1 = c1b[1], a2 = c1b[2];
        #pragma unroll
        for (int kh = 0; kh < 3; kh++)
            #pragma unroll
            for (int kw = 0; kw < 3; kw++) {
                const float* s = &sec[((oh + kh) * 16 + (ow + kw)) * 3];
                const float* w = &c1k[(kh * 3 + kw) * 9];
                #pragma unroll
                for (int ic = 0; ic < 3; ic++) {
                    const float sv = s[ic];
                    a0 += sv * w[ic * 3 + 0];
                    a1 += sv * w[ic * 3 + 1];
                    a2 += sv * w[ic * 3 + 2];
                }
            }
        c1o[t * 3 + 0] = fmaxf(a0, 0.0f);
        c1o[t * 3 + 1] = fmaxf(a1, 0.0f);
        c1o[t * 3 + 2] = fmaxf(a2, 0.0f);
    }
    __syncthreads();

    if (t < 144) {
        const int oh = t / 12;
        const int ow = t - oh * 12;
        float a0 = c2b[0], a1 = c2b[1], a2 = c2b[2];
        #pragma unroll
        for (int kh = 0; kh < 3; kh++)
            #pragma unroll
            for (int kw = 0; kw < 3; kw++) {
                const float* s = &c1o[((oh + kh) * 14 + (ow + kw)) * 3];
                const float* w = &c2k[(kh * 3 + kw) * 9];
                #pragma unroll
                for (int ic = 0; ic < 3; ic++) {
                    const float sv = s[ic];
                    a0 += sv * w[ic * 3 + 0];
                    a1 += sv * w[ic * 3 + 1];
                    a2 += sv * w[ic * 3 + 2];
                }
            }
        float* dst = g_xs + b * 432 + t * 3;
        dst[0] = fmaxf(a0, 0.0f);
        dst[1] = fmaxf(a1, 0.0f);
        dst[2] = fmaxf(a2, 0.0f);
    }
}

// ===========================================================================
// K2: dense partial. 128 blocks = 32 unit-tiles (8 units) x 4 k-tiles (108).
// atomicAdd into g_y (bias pre-initialized). ReLU applied by consumer (K3).
// ===========================================================================
__global__ __launch_bounds__(256, 1)
void k2_dense(const float* __restrict__ dw)
{
    const int ut = blockIdx.x & 31;
    const int kt = blockIdx.x >> 5;
    const int t  = threadIdx.x;
    const int k0 = kt * 108;

    __shared__ float axs[64][112];
    __shared__ float wts[108][12];

    for (int i = t; i < 64 * 27; i += 256) {
        const int row = i / 27;
        const int c4  = i - row * 27;
        const float4 v = *(const float4*)(g_xs + row * 432 + k0 + c4 * 4);
        *(float4*)&axs[row][c4 * 4] = v;
    }
    if (t < 216) {
        const int row = t >> 1;
        const int h   = t & 1;
        const float4 w = *(const float4*)(dw + (size_t)(k0 + row) * U + ut * 8 + h * 4);
        *(float4*)&wts[row][h * 4] = w;
    }
    __syncthreads();

    const int u2 = t & 3;
    const int bp = t >> 2;
    float a0 = 0.f, a1 = 0.f, a2 = 0.f, a3 = 0.f;
    #pragma unroll 2
    for (int k = 0; k < 108; k += 2) {
        const float x0 = axs[bp][k];
        const float x1 = axs[bp][k + 1];
        const float2 w0 = *(const float2*)&wts[k][u2 * 2];
        const float2 w1 = *(const float2*)&wts[k + 1][u2 * 2];
        a0 += x0 * w0.x; a1 += x0 * w0.y;
        a2 += x1 * w1.x; a3 += x1 * w1.y;
    }
    const int u = ut * 8 + u2 * 2;
    atomicAdd(&g_y[bp * U + u],     a0 + a2);
    atomicAdd(&g_y[bp * U + u + 1], a1 + a3);
}

// ===========================================================================
// K3: LSTM partial. 128 blocks = 16 col-tiles (64 z-cols) x 8 k-tiles (64).
//   kt<4 : acts = relu(g_y),  weights = lstm_k
//   kt>=4: acts = h0,         weights = lstm_rk
// Partials -> g_zp[kt], unit-major [b][u*4+gate] (plain stores).
// ===========================================================================
__global__ __launch_bounds__(256, 1)
void k3_lstm(const float* __restrict__ h0,
             const float* __restrict__ lk, const float* __restrict__ lrk)
{
    __shared__ float act[64][68];   // [batch][k]
    __shared__ float wt [64][68];   // [k][col]

    const int ct = blockIdx.x & 15;
    const int kt = blockIdx.x >> 4;
    const int t  = threadIdx.x;

    if (kt < 4) {
        const float* base = g_y + kt * 64;
        for (int i = t; i < 64 * 16; i += 256) {
            const int row = i >> 4;
            const int c4  = i & 15;
            float4 v = *(const float4*)(base + row * U + c4 * 4);
            v.x = fmaxf(v.x, 0.f); v.y = fmaxf(v.y, 0.f);
            v.z = fmaxf(v.z, 0.f); v.w = fmaxf(v.w, 0.f);
            *(float4*)&act[row][c4 * 4] = v;
        }
    } else {
        const float* base = h0 + (kt - 4) * 64;
        for (int i = t; i < 64 * 16; i += 256) {
            const int row = i >> 4;
            const int c4  = i & 15;
            const float4 v = *(const float4*)(base + row * U + c4 * 4);
            *(float4*)&act[row][c4 * 4] = v;
        }
    }
    {
        const float* wsrc = (kt < 4) ? (lk + (size_t)kt * 64 * 1024)
                                     : (lrk + (size_t)(kt - 4) * 64 * 1024);
        for (int i = t; i < 64 * 16; i += 256) {
            const int row = i >> 4;
            const int c4  = i & 15;
            const float4 w = *(const float4*)(wsrc + (size_t)row * 1024 + ct * 64 + c4 * 4);
            *(float4*)&wt[row][c4 * 4] = w;
        }
    }
    __syncthreads();

    const int c4 = t & 15;       // col group: 4 cols ct*64 + c4*4 ..
    const int bq = t >> 4;       // batches bq, bq+16, bq+32, bq+48
    float s0x = 0.f, s0y = 0.f, s0z = 0.f, s0w = 0.f;
    float s1x = 0.f, s1y = 0.f, s1z = 0.f, s1w = 0.f;
    float s2x = 0.f, s2y = 0.f, s2z = 0.f, s2w = 0.f;
    float s3x = 0.f, s3y = 0.f, s3z = 0.f, s3w = 0.f;

    #pragma unroll 4
    for (int kk = 0; kk < 64; kk++) {
        const float4 w = *(const float4*)&wt[kk][c4 * 4];
        const float a0 = act[bq     ][kk];
        const float a1 = act[bq + 16][kk];
        const float a2 = act[bq + 32][kk];
        const float a3 = act[bq + 48][kk];
        s0x += a0 * w.x; s0y += a0 * w.y; s0z += a0 * w.z; s0w += a0 * w.w;
        s1x += a1 * w.x; s1y += a1 * w.y; s1z += a1 * w.z; s1w += a1 * w.w;
        s2x += a2 * w.x; s2y += a2 * w.y; s2z += a2 * w.z; s2w += a2 * w.w;
        s3x += a3 * w.x; s3y += a3 * w.y; s3z += a3 * w.z; s3w += a3 * w.w;
    }

    const int gg = ct >> 2;              // gate 0..3
    const int u0 = (ct & 3) * 64 + c4 * 4;
    {
        float* d = &g_zp[kt][bq][u0 * 4 + gg];
        d[0] = s0x; d[4] = s0y; d[8] = s0z; d[12] = s0w;
    }
    {
        float* d = &g_zp[kt][bq + 16][u0 * 4 + gg];
        d[0] = s1x; d[4] = s1y; d[8] = s1z; d[12] = s1w;
    }
    {
        float* d = &g_zp[kt][bq + 32][u0 * 4 + gg];
        d[0] = s2x; d[4] = s2y; d[8] = s2z; d[12] = s2w;
    }
    {
        float* d = &g_zp[kt][bq + 48][u0 * 4 + gg];
        d[0] = s3x; d[4] = s3y; d[8] = s3z; d[12] = s3w;
    }
}

// ===========================================================================
// K4: per-batch tail. 64 blocks x 512 threads; block = batch b.
//  Phase A (t<256): gates — sum 8 g_zp slices + lb, nonlinearity,
//                   write h_new/c_new to out, stash h in smem.
//  Phase B: nsc1 GEMV — thread (u4 = t&63, kc = t>>6): 4 units x 32-k chunk.
//           32 x LDG.128 of w1 per thread, part sums -> smem, reduce+relu.
//  Phase C (t<96): nsc2 — 3 outputs via warp-strided dot + shfl reduce.
// ===========================================================================
__global__ __launch_bounds__(512, 2)
void k4_tail(const float* __restrict__ c0in, const float* __restrict__ lb,
             const float* __restrict__ w1,  const float* __restrict__ b1,
             const float* __restrict__ w2,  const float* __restrict__ b2v,
             float* __restrict__ out)
{
    const int b = blockIdx.x;
    const int t = threadIdx.x;

    __shared__ float hs[U];          // h_new for this batch
    __shared__ float part[8][U];     // nsc1 split-k partials
    __shared__ float ns[U];          // nsc1 output

    // ---- Phase A: gates (threads 0..255, u = t) ----
    if (t < U) {
        const int u = t;
        float zi = 0.f, zf = 0.f, zg = 0.f, zo = 0.f;
        #pragma unroll
        for (int s = 0; s < 8; s++) {
            const float4 z = *(const float4*)&g_zp[s][b][u * 4];
            zi += z.x; zf += z.y; zg += z.z; zo += z.w;
        }
        zi += lb[u];
        zf += lb[U + u];
        zg += lb[2 * U + u];
        zo += lb[3 * U + u];

        const float cprev = c0in[b * U + u];
        const float cn = sigmoidf_(zf) * cprev + sigmoidf_(zi) * tanhf(zg);
        const float hn = sigmoidf_(zo) * tanhf(cn);
        out[b * U + u]         = hn;
        out[B * U + b * U + u] = cn;
        hs[u] = hn;
    }
    __syncthreads();

    // ---- Phase B: nsc1 GEMV: ns = relu(hs @ w1 + b1) ----
    {
        const int u4 = t & 63;       // unit group: units u4*4 .. u4*4+3
        const int kc = t >> 6;       // k chunk 0..7 (32 deep)
        const int k0 = kc * 32;
        float4 acc = make_float4(0.f, 0.f, 0.f, 0.f);
        #pragma unroll 4
        for (int k = k0; k < k0 + 32; k++) {
            const float hv = hs[k];
            const float4 w = *(const float4*)(w1 + (size_t)k * U + u4 * 4);
            acc.x += hv * w.x; acc.y += hv * w.y;
            acc.z += hv * w.z; acc.w += hv * w.w;
        }
        *(float4*)&part[kc][u4 * 4] = acc;
    }
    __syncthreads();
    if (t < 64) {
        float4 s = make_float4(0.f, 0.f, 0.f, 0.f);
        #pragma unroll
        for (int kc = 0; kc < 8; kc++) {
            const float4 p = *(const float4*)&part[kc][t * 4];
            s.x += p.x; s.y += p.y; s.z += p.z; s.w += p.w;
        }
        const float4 bias = *(const float4*)(b1 + t * 4);
        ns[t * 4 + 0] = fmaxf(s.x + bias.x, 0.0f);
        ns[t * 4 + 1] = fmaxf(s.y + bias.y, 0.0f);
        ns[t * 4 + 2] = fmaxf(s.z + bias.z, 0.0f);
        ns[t * 4 + 3] = fmaxf(s.w + bias.w, 0.0f);
    }
    __syncthreads();

    // ---- Phase C: nsc2 (3 warps) ----
    if (t < 96) {
        const int g = t >> 5;
        const int l = t & 31;
        float s = 0.0f;
        #pragma unroll
        for (int i = 0; i < 8; i++) {
            const int k = l + i * 32;
            s += ns[k] * w2[k * 3 + g];
        }
        #pragma unroll
        for (int o = 16; o > 0; o >>= 1)
            s += __shfl_down_sync(0xffffffffu, s, o);
        if (l == 0)
            out[2 * B * U + b * 3 + g] = sigmoidf_(s + b2v[g]);
    }
}

// ===========================================================================
extern "C" void kernel_launch(void* const* d_in, const int* in_sizes, int n_in,
                              void* d_out, int out_size)
{
    const float* image   = (const float*)d_in[0];
    const float* section = (const float*)d_in[1];
    const float* h0      = (const float*)d_in[2];
    const float* c0      = (const float*)d_in[3];
    const float* conv1_k = (const float*)d_in[4];
    const float* conv1_b = (const float*)d_in[5];
    const float* conv2_k = (const float*)d_in[6];
    const float* conv2_b = (const float*)d_in[7];
    const float* dense_w = (const float*)d_in[8];
    const float* dense_b = (const float*)d_in[9];
    const float* lstm_k  = (const float*)d_in[10];
    const float* lstm_rk = (const float*)d_in[11];
    const float* lstm_b  = (const float*)d_in[12];
    const float* nsc_w1  = (const float*)d_in[13];
    const float* nsc_b1  = (const float*)d_in[14];
    const float* nsc_w2  = (const float*)d_in[15];
    const float* nsc_b2  = (const float*)d_in[16];
    float* out = (float*)d_out;

    k1_front<<<B, 256>>>(image, section, conv1_k, conv1_b,
                         conv2_k, conv2_b, dense_b);
    k2_dense<<<128, 256>>>(dense_w);
    k3_lstm<<<128, 256>>>(h0, lstm_k, lstm_rk);
    k4_tail<<<B, 512>>>(c0, lstm_b, nsc_w1, nsc_b1, nsc_w2, nsc_b2, out);
}